// round 12
// baseline (speedup 1.0000x reference)
#include <cuda_runtime.h>
#include <cuda_bf16.h>
#include <math_constants.h>

#define B 128
#define P 8732
#define C 21
#define NEG_POS_RATIO 3
#define TILE_A 256
#define NT_A 256
#define NBLK_ROW ((P + TILE_A - 1) / TILE_A)   // 35
#define NT_B 1024
#define KPT 9                          // ceil(8732/1024)
#define HW 16384                       // packed hist words per row (2^16 bins / 4)
#define LCAP 1024

__device__ unsigned g_keys[(size_t)B * P];
__device__ unsigned g_hist[(size_t)B * HW];    // 8.4 MB, byte-packed counts
__device__ float    g_rowf[B][4];
__device__ int      g_rowi[B];
__device__ float    g_acc[4];
__device__ int      g_done;

__device__ __forceinline__ unsigned f2key(float f) {
    unsigned b = __float_as_uint(f);
    return (b & 0x80000000u) ? ~b : (b | 0x80000000u);
}
__device__ __forceinline__ float key2f(unsigned k) {
    unsigned b = (k & 0x80000000u) ? (k & 0x7FFFFFFFu) : ~k;
    return __uint_as_float(b);
}
__device__ __forceinline__ float warp_sum_f(float v) {
    #pragma unroll
    for (int o = 16; o > 0; o >>= 1) v += __shfl_down_sync(0xFFFFFFFFu, v, o);
    return v;
}
__device__ __forceinline__ unsigned smem_u32(const void* p) {
    return (unsigned)__cvta_generic_to_shared(p);
}

// ================= kernel A: streaming (grid 35 x 128, 256 thr) =================
__global__ void k_stream(const float* __restrict__ conf,
                         const float* __restrict__ pred,
                         const int*   __restrict__ labels,
                         const float* __restrict__ gt,
                         const float* __restrict__ mask) {
    __shared__ float sc[TILE_A * C];
    __shared__ float sredf[3][8];
    __shared__ int   sredi[8];

    const int b  = blockIdx.y;
    const int p0 = blockIdx.x * TILE_A;
    const int t  = threadIdx.x;
    const int wid = t >> 5, lane = t & 31;
    const size_t rb = (size_t)b * P;
    const int nanch = min(TILE_A, P - p0);
    const int nf4   = (nanch * C) >> 2;

    {
        const unsigned sb = smem_u32(sc);
        const float4* src = (const float4*)(conf + (rb + p0) * C);
        for (int i = t; i < nf4; i += NT_A) {
            asm volatile("cp.async.cg.shared.global [%0], [%1], 16;"
                         :: "r"(sb + i * 16), "l"(src + i));
        }
        asm volatile("cp.async.commit_group;");
    }
    int lab = 0; float mk = 0.0f;
    if (t < nanch) { lab = labels[rb + p0 + t]; mk = mask[rb + p0 + t]; }
    asm volatile("cp.async.wait_group 0;");
    __syncthreads();

    float posc = 0.0f, regl = 0.0f, msum = 0.0f;
    int   npos = 0;

    if (t < nanch) {
        const float* c = sc + t * C;
        float v[C];
        #pragma unroll
        for (int j = 0; j < C; j++) v[j] = c[j];

        float m = v[0];
        #pragma unroll
        for (int j = 1; j < C; j++) m = fmaxf(m, v[j]);
        float s0 = 0.0f, s1 = 0.0f, s2 = 0.0f;
        #pragma unroll
        for (int j = 0; j < C; j += 3) s0 += __expf(v[j] - m);
        #pragma unroll
        for (int j = 1; j < C; j += 3) s1 += __expf(v[j] - m);
        #pragma unroll
        for (int j = 2; j < C; j += 3) s2 += __expf(v[j] - m);
        const float lse = __logf(s0 + s1 + s2) + m;

        msum = mk;
        unsigned key = 0u;
        if (lab > 0) {
            npos = 1;
            float clab = v[0];
            #pragma unroll
            for (int j = 1; j < C; j++) clab = (lab == j) ? v[j] : clab;
            posc = mk * (lse - clab);
            const size_t gi = rb + p0 + t;
            const float4 pv = *(const float4*)(pred + gi * 4);
            const float4 gv = *(const float4*)(gt   + gi * 4);
            float r = 0.0f, d, ad;
            d = pv.x - gv.x; ad = fabsf(d); r += (ad < 1.0f) ? 0.5f * d * d : ad - 0.5f;
            d = pv.y - gv.y; ad = fabsf(d); r += (ad < 1.0f) ? 0.5f * d * d : ad - 0.5f;
            d = pv.z - gv.z; ad = fabsf(d); r += (ad < 1.0f) ? 0.5f * d * d : ad - 0.5f;
            d = pv.w - gv.w; ad = fabsf(d); r += (ad < 1.0f) ? 0.5f * d * d : ad - 0.5f;
            regl = mk * r;
        } else {
            key = f2key(lse - v[0]);
        }
        g_keys[rb + p0 + t] = key;
        const unsigned bin = key >> 16;            // 16-bit bin
        atomicAdd(&g_hist[(size_t)b * HW + (bin >> 2)], 1u << ((bin & 3u) * 8));
    }

    posc = warp_sum_f(posc);
    regl = warp_sum_f(regl);
    msum = warp_sum_f(msum);
    npos = __reduce_add_sync(0xFFFFFFFFu, npos);
    if (lane == 0) { sredf[0][wid] = posc; sredf[1][wid] = regl; sredf[2][wid] = msum; sredi[wid] = npos; }
    __syncthreads();
    if (t == 0) {
        float a0 = 0, a1 = 0, a2 = 0; int a3 = 0;
        #pragma unroll
        for (int w = 0; w < 8; w++) { a0 += sredf[0][w]; a1 += sredf[1][w]; a2 += sredf[2][w]; a3 += sredi[w]; }
        if (a0 != 0.0f) atomicAdd(&g_rowf[b][0], a0);
        if (a1 != 0.0f) atomicAdd(&g_rowf[b][1], a1);
        atomicAdd(&g_rowf[b][2], a2);
        if (a3) atomicAdd(&g_rowi[b], a3);
    }
}

// ========== kernel B: fine-hist scan -> direct sum + tiny exact tie fix ==========
__global__ __launch_bounds__(NT_B, 1)
void k_sel2(float* __restrict__ out) {
    const int b    = blockIdx.x;
    const int t    = threadIdx.x;
    const int wid  = t >> 5;
    const int lane = t & 31;

    __shared__ unsigned s_list[LCAP];      // 4 KB
    __shared__ unsigned swsum[32];
    __shared__ unsigned s_woff[32];
    __shared__ float    sredf[32];
    __shared__ unsigned s_T, s_kk;
    __shared__ int      s_L;
    __shared__ float    s_negtie;
    __shared__ int      sk;
    __shared__ bool     sLast;

    const size_t rb = (size_t)b * P;

    // 1. load this row's keys
    unsigned keys[KPT];
    #pragma unroll
    for (int i = 0; i < KPT; i++) {
        const int idx = t + i * NT_B;
        keys[i] = (idx < P) ? g_keys[rb + idx] : 0u;
    }

    // 2. load my 16 packed hist words, byte-sum via dp4a
    unsigned* hrow = g_hist + (size_t)b * HW;
    union { uint4 q[4]; unsigned w[16]; } h;
    #pragma unroll
    for (int j = 0; j < 4; j++) h.q[j] = ((const uint4*)hrow)[t * 4 + j];
    int ts = 0;
    #pragma unroll
    for (int j = 0; j < 16; j++) ts = __dp4a((int)h.w[j], 0x01010101, ts);

    // inclusive suffix within warp (higher lane = higher bins)
    int v = ts;
    #pragma unroll
    for (int off = 1; off < 32; off <<= 1) {
        int u = __shfl_down_sync(0xFFFFFFFFu, v, off);
        if (lane + off < 32) v += u;
    }
    if (lane == 0) swsum[wid] = (unsigned)v;
    if (t == 0) { sk = g_rowi[b] * NEG_POS_RATIO; s_T = 0u; s_kk = 0u; s_negtie = 0.0f; s_L = 0; }
    __syncthreads();
    if (wid == 0) {
        unsigned sv = swsum[lane];
        #pragma unroll
        for (int off = 1; off < 32; off <<= 1) {
            unsigned u = __shfl_down_sync(0xFFFFFFFFu, sv, off);
            if (lane + off < 32) sv += u;
        }
        swsum[lane] = sv;                  // inclusive suffix over warps
    }
    __syncthreads();
    const int k = sk;

    if (k > 0) {
        // 3. locate threshold bin T and rank kk within it (unique owning thread)
        unsigned run = ((wid < 31) ? swsum[wid + 1] : 0u) + (unsigned)(v - ts);
        #pragma unroll
        for (int w = 15; w >= 0; w--) {
            const unsigned word = h.w[w];
            #pragma unroll
            for (int byi = 3; byi >= 0; byi--) {
                const unsigned c = (word >> (byi * 8)) & 255u;
                if (c && run < (unsigned)k && run + c >= (unsigned)k) {
                    s_T  = (unsigned)((t * 16 + w) * 4 + byi);
                    s_kk = (unsigned)k - run;
                }
                run += c;
            }
        }
    }
    // zero hist row for next replay (all threads, regardless of k)
    {
        const uint4 z = {0u, 0u, 0u, 0u};
        #pragma unroll
        for (int j = 0; j < 4; j++) ((uint4*)hrow)[t * 4 + j] = z;
    }
    __syncthreads();

    float negsum = 0.0f;
    if (k > 0) {
        const unsigned T  = s_T;
        const unsigned kk = s_kk;

        // 4. direct sum of definitely-selected keys; count bin-T keys per warp
        float dsum = 0.0f;
        int wcnt = 0;
        #pragma unroll
        for (int i = 0; i < KPT; i++) {
            const unsigned bin = keys[i] >> 16;
            if (bin > T) dsum += key2f(keys[i]);
            const bool inT = (T != 0u) && (bin == T) && (t + i * NT_B < P);
            wcnt += __popc(__ballot_sync(0xFFFFFFFFu, inT));
        }
        if (lane == 0) swsum[wid] = (unsigned)wcnt;
        __syncthreads();
        if (wid == 0) {                        // ascending exclusive scan of warp counts
            unsigned x = swsum[lane];
            unsigned inc = x;
            #pragma unroll
            for (int off = 1; off < 32; off <<= 1) {
                unsigned u = __shfl_up_sync(0xFFFFFFFFu, inc, off);
                if (lane >= off) inc += u;
            }
            s_woff[lane] = inc - x;
            if (lane == 31) s_L = (int)inc;
        }
        __syncthreads();
        const int L = s_L;

        // 5. compact bin-T keys (no atomics)
        unsigned off = s_woff[wid];
        #pragma unroll
        for (int i = 0; i < KPT; i++) {
            const unsigned bin = keys[i] >> 16;
            const bool inT = (T != 0u) && (bin == T) && (t + i * NT_B < P);
            const unsigned bm = __ballot_sync(0xFFFFFFFFu, inT);
            if (inT) {
                const unsigned pos = off + __popc(bm & ((1u << lane) - 1u));
                if (pos < LCAP) s_list[pos] = keys[i];
            }
            off += __popc(bm);
        }
        __syncthreads();

        // 6. warp0: exact bisection over low 16 bits of the tiny bin-T list
        if (wid == 0 && T != 0u && kk >= 1u) {
            if (L <= LCAP) {
                unsigned prefix = T << 16;
                for (int bit = 15; bit >= 0; bit--) {
                    const unsigned cand = prefix | (1u << bit);
                    int c = 0;
                    for (int j = lane; j < L; j += 32) c += (s_list[j] >= cand);
                    c = __reduce_add_sync(0xFFFFFFFFu, c);
                    if ((unsigned)c >= kk) prefix = cand;
                }
                int cg = 0; float sg = 0.0f;
                for (int j = lane; j < L; j += 32) {
                    const unsigned kj = s_list[j];
                    if (kj > prefix) { cg++; sg += key2f(kj); }
                }
                cg = __reduce_add_sync(0xFFFFFFFFu, cg);
                sg = warp_sum_f(sg);
                if (lane == 0) s_negtie = sg + (float)((int)kk - cg) * key2f(prefix);
            } else if (lane == 0) {
                // incomplete list (unreachable for sane data): bin-midpoint approx
                s_negtie = (float)kk * key2f((T << 16) | 0x8000u);
            }
        }

        // 7. block reduce dsum
        dsum = warp_sum_f(dsum);
        if (lane == 0) sredf[wid] = dsum;
        __syncthreads();
        if (t == 0) {
            float stot = 0.0f;
            #pragma unroll
            for (int w = 0; w < 32; w++) stot += sredf[w];
            negsum = stot + s_negtie;
        }
    }

    // 8. fold row into globals, reset row scratch, last block finalizes
    if (t == 0) {
        atomicAdd(&g_acc[0], g_rowf[b][0]);
        atomicAdd(&g_acc[1], g_rowf[b][1]);
        atomicAdd(&g_acc[2], g_rowf[b][2]);
        if (negsum != 0.0f) atomicAdd(&g_acc[3], negsum);
        g_rowf[b][0] = 0.0f; g_rowf[b][1] = 0.0f; g_rowf[b][2] = 0.0f;
        g_rowi[b] = 0;
        __threadfence();
        const int prev = atomicAdd(&g_done, 1);
        sLast = (prev == B - 1);
    }
    __syncthreads();
    if (sLast && t == 0) {
        volatile float* a = g_acc;
        const float inv = 1.0f / a[2];
        out[0] = a[1] * inv;
        out[1] = (a[0] + a[3]) * inv;
        a[0] = 0.0f; a[1] = 0.0f; a[2] = 0.0f; a[3] = 0.0f;
        g_done = 0;
    }
}

extern "C" void kernel_launch(void* const* d_in, const int* in_sizes, int n_in,
                              void* d_out, int out_size) {
    const float* conf   = (const float*)d_in[0];
    const float* pred   = (const float*)d_in[1];
    const int*   labels = (const int*)d_in[2];
    const float* gt     = (const float*)d_in[3];
    const float* mask   = (const float*)d_in[4];
    float* out = (float*)d_out;

    dim3 ga(NBLK_ROW, B);
    k_stream<<<ga, NT_A>>>(conf, pred, labels, gt, mask);
    k_sel2<<<B, NT_B>>>(out);
}